// round 1
// baseline (speedup 1.0000x reference)
#include <cuda_runtime.h>
#include <math.h>

#define N_NODES 100000
#define N_EDGES 1600000

// ---- scratch (device globals: allocation-free per harness rules) ----
__device__ float g_h1[N_NODES * 64];     // layer1 projected features
__device__ float g_ssrc1[N_NODES * 8];   // per-node src attention score
__device__ float g_sdst1[N_NODES * 8];
__device__ float g_out1[N_NODES * 64];   // layer1 unnormalized aggregation
__device__ float g_den1[N_NODES * 8];    // softmax denominators
__device__ float g_h2[N_NODES * 40];
__device__ float g_ssrc2[N_NODES];
__device__ float g_sdst2[N_NODES];
__device__ float g_out2[N_NODES * 40];
__device__ float g_den2[N_NODES];

__device__ __forceinline__ void red_add_v4(float* p, float a, float b, float c, float d) {
    asm volatile("red.global.add.v4.f32 [%0], {%1,%2,%3,%4};"
                 :: "l"(p), "f"(a), "f"(b), "f"(c), "f"(d) : "memory");
}

// ---------------- clear accumulators ----------------
__global__ void clear_kernel() {
    int i = blockIdx.x * blockDim.x + threadIdx.x;
    int stride = gridDim.x * blockDim.x;
    float4 z = make_float4(0.f, 0.f, 0.f, 0.f);
    for (int t = i; t < N_NODES * 64 / 4; t += stride) ((float4*)g_out1)[t] = z;
    for (int t = i; t < N_NODES * 8 / 4;  t += stride) ((float4*)g_den1)[t] = z;
    for (int t = i; t < N_NODES * 40 / 4; t += stride) ((float4*)g_out2)[t] = z;
    for (int t = i; t < N_NODES / 4;      t += stride) ((float4*)g_den2)[t] = z;
}

// ---------------- GEMM1: h1 = x @ W1, + s_src1/s_dst1 epilogue ----------------
// block: 128 threads, 128 nodes/block, 64 cols. thread = (ty 0..15, tx 0..7),
// 8 nodes x 8 cols register tile. cols tx*8..tx*8+7 == head tx dims 0..7.
__global__ void __launch_bounds__(128) gemm1_kernel(
    const float* __restrict__ x, const float* __restrict__ W1,
    const float* __restrict__ asrc, const float* __restrict__ adst)
{
    __shared__ float sx[128 * 33];   // [node][k] stride 33 (conflict-free)
    __shared__ float sW[32 * 64];    // [k][col]
    int tid = threadIdx.x;
    int ty = tid >> 3, tx = tid & 7;
    int base = blockIdx.x * 128;

    float acc[8][8];
#pragma unroll
    for (int i = 0; i < 8; i++)
#pragma unroll
        for (int j = 0; j < 8; j++) acc[i][j] = 0.f;

    for (int k0 = 0; k0 < 128; k0 += 32) {
        // load x tile: 128 nodes x 32 k
#pragma unroll
        for (int t = tid; t < 1024; t += 128) {
            int row = t >> 3, q = t & 7;
            int node = base + row;
            float4 v = make_float4(0.f, 0.f, 0.f, 0.f);
            if (node < N_NODES)
                v = *(const float4*)&x[(long long)node * 128 + k0 + q * 4];
            float* sp = &sx[row * 33 + q * 4];
            sp[0] = v.x; sp[1] = v.y; sp[2] = v.z; sp[3] = v.w;
        }
        // load W tile: 32 x 64
#pragma unroll
        for (int t = tid; t < 512; t += 128) {
            int r = t >> 4, c4 = t & 15;
            *(float4*)&sW[r * 64 + c4 * 4] = *(const float4*)&W1[(k0 + r) * 64 + c4 * 4];
        }
        __syncthreads();
#pragma unroll 8
        for (int kk = 0; kk < 32; kk++) {
            float xa[8];
#pragma unroll
            for (int i = 0; i < 8; i++) xa[i] = sx[(ty * 8 + i) * 33 + kk];
            float4 w0 = *(float4*)&sW[kk * 64 + tx * 8];
            float4 w1 = *(float4*)&sW[kk * 64 + tx * 8 + 4];
            float wb[8] = {w0.x, w0.y, w0.z, w0.w, w1.x, w1.y, w1.z, w1.w};
#pragma unroll
            for (int i = 0; i < 8; i++)
#pragma unroll
                for (int j = 0; j < 8; j++) acc[i][j] += xa[i] * wb[j];
        }
        __syncthreads();
    }

    float as[8], ad[8];
#pragma unroll
    for (int j = 0; j < 8; j++) { as[j] = __ldg(&asrc[tx * 8 + j]); ad[j] = __ldg(&adst[tx * 8 + j]); }

#pragma unroll
    for (int i = 0; i < 8; i++) {
        int node = base + ty * 8 + i;
        if (node < N_NODES) {
            *(float4*)&g_h1[(long long)node * 64 + tx * 8] =
                make_float4(acc[i][0], acc[i][1], acc[i][2], acc[i][3]);
            *(float4*)&g_h1[(long long)node * 64 + tx * 8 + 4] =
                make_float4(acc[i][4], acc[i][5], acc[i][6], acc[i][7]);
            float ss = 0.f, sd = 0.f;
#pragma unroll
            for (int j = 0; j < 8; j++) { ss += acc[i][j] * as[j]; sd += acc[i][j] * ad[j]; }
            g_ssrc1[node * 8 + tx] = ss;
            g_sdst1[node * 8 + tx] = sd;
        }
    }
}

// ---------------- edge pass 1: scatter w and w*h_src ----------------
// 16 lanes per edge. lane l covers out cols [4l, 4l+4) -> head l>>1.
__global__ void __launch_bounds__(256) edge1_kernel(
    const int* __restrict__ src, const int* __restrict__ dst,
    const float* __restrict__ ea, const float* __restrict__ aedge)
{
    int l = threadIdx.x & 15;
    int g = (blockIdx.x * blockDim.x + threadIdx.x) >> 4;
    int ng = (gridDim.x * blockDim.x) >> 4;
    int hd = l >> 1;
    float ae = __ldg(&aedge[hd]);
    for (int e = g; e < N_EDGES; e += ng) {
        int s = __ldg(&src[e]);
        int d = __ldg(&dst[e]);
        float lg = g_ssrc1[s * 8 + hd] + g_sdst1[d * 8 + hd] + __ldg(&ea[e]) * ae;
        lg = lg > 0.f ? lg : 0.2f * lg;           // leaky relu 0.2
        float w = __expf(lg);                     // no max-shift needed (bounded logits)
        if ((l & 1) == 0) atomicAdd(&g_den1[d * 8 + hd], w);
        float4 hv = *(const float4*)&g_h1[(long long)s * 64 + l * 4];
        red_add_v4(&g_out1[(long long)d * 64 + l * 4], w * hv.x, w * hv.y, w * hv.z, w * hv.w);
    }
}

// ---------------- GEMM2: h2 = elu(out1/den1) @ W2, + s_src2/s_dst2 ----------------
// block: 256 threads, 64 nodes/block, 4 threads/node x 10 cols each.
__global__ void __launch_bounds__(256) gemm2_kernel(
    const float* __restrict__ W2, const float* __restrict__ asrc,
    const float* __restrict__ adst)
{
    __shared__ float sx[64 * 65];    // [node][k], stride 65
    __shared__ float sW[64 * 40];
    int tid = threadIdx.x;
    int base = blockIdx.x * 64;

    for (int t = tid; t < 2560; t += 256) sW[t] = W2[t];

    // load + normalize + elu the layer1 output tile
    for (int t = tid; t < 1024; t += 256) {
        int row = t >> 4, q = t & 15;      // k = q*4, head = q>>1
        int node = base + row;
        float4 v = make_float4(0.f, 0.f, 0.f, 0.f);
        if (node < N_NODES) {
            v = *(const float4*)&g_out1[(long long)node * 64 + q * 4];
            float inv = 1.0f / (g_den1[node * 8 + (q >> 1)] + 1e-16f);
            v.x *= inv; v.y *= inv; v.z *= inv; v.w *= inv;
            v.x = v.x > 0.f ? v.x : expm1f(v.x);
            v.y = v.y > 0.f ? v.y : expm1f(v.y);
            v.z = v.z > 0.f ? v.z : expm1f(v.z);
            v.w = v.w > 0.f ? v.w : expm1f(v.w);
        }
        float* sp = &sx[row * 65 + q * 4];
        sp[0] = v.x; sp[1] = v.y; sp[2] = v.z; sp[3] = v.w;
    }
    __syncthreads();

    int nl = tid >> 2, q = tid & 3;
    int cbase = q * 10;
    float acc[10];
#pragma unroll
    for (int c = 0; c < 10; c++) acc[c] = 0.f;
#pragma unroll 8
    for (int k = 0; k < 64; k++) {
        float xv = sx[nl * 65 + k];
#pragma unroll
        for (int c = 0; c < 10; c++) acc[c] += xv * sW[k * 40 + cbase + c];
    }

    int node = base + nl;
    float ss = 0.f, sd = 0.f;
#pragma unroll
    for (int c = 0; c < 10; c++) {
        ss += acc[c] * __ldg(&asrc[cbase + c]);
        sd += acc[c] * __ldg(&adst[cbase + c]);
    }
    ss += __shfl_xor_sync(0xffffffffu, ss, 1); ss += __shfl_xor_sync(0xffffffffu, ss, 2);
    sd += __shfl_xor_sync(0xffffffffu, sd, 1); sd += __shfl_xor_sync(0xffffffffu, sd, 2);
    if (node < N_NODES) {
#pragma unroll
        for (int c = 0; c < 10; c++) g_h2[(long long)node * 40 + cbase + c] = acc[c];
        if (q == 0) { g_ssrc2[node] = ss; g_sdst2[node] = sd; }
    }
}

// ---------------- edge pass 2: 1 head x 40 dims ----------------
__global__ void __launch_bounds__(256) edge2_kernel(
    const int* __restrict__ src, const int* __restrict__ dst,
    const float* __restrict__ ea, const float* __restrict__ aedge2)
{
    int l = threadIdx.x & 15;
    int g = (blockIdx.x * blockDim.x + threadIdx.x) >> 4;
    int ng = (gridDim.x * blockDim.x) >> 4;
    float ae = __ldg(&aedge2[0]);
    for (int e = g; e < N_EDGES; e += ng) {
        int s = __ldg(&src[e]);
        int d = __ldg(&dst[e]);
        float lg = g_ssrc2[s] + g_sdst2[d] + __ldg(&ea[e]) * ae;
        lg = lg > 0.f ? lg : 0.2f * lg;
        float w = __expf(lg);
        if (l == 0) atomicAdd(&g_den2[d], w);
        if (l < 10) {
            float4 hv = *(const float4*)&g_h2[(long long)s * 40 + l * 4];
            red_add_v4(&g_out2[(long long)d * 40 + l * 4], w * hv.x, w * hv.y, w * hv.z, w * hv.w);
        }
    }
}

// ---------------- finalize: normalize + log_softmax(40) ----------------
__global__ void __launch_bounds__(256) finalize_kernel(float* __restrict__ out)
{
    int n = (blockIdx.x * blockDim.x + threadIdx.x) >> 5;
    int lane = threadIdx.x & 31;
    if (n >= N_NODES) return;
    float inv = 1.0f / (g_den2[n] + 1e-16f);
    float v1 = g_out2[(long long)n * 40 + lane] * inv;
    float v2 = (lane < 8) ? g_out2[(long long)n * 40 + 32 + lane] * inv : -INFINITY;
    float m = fmaxf(v1, v2);
#pragma unroll
    for (int o = 16; o; o >>= 1) m = fmaxf(m, __shfl_xor_sync(0xffffffffu, m, o));
    float s = __expf(v1 - m) + ((lane < 8) ? __expf(v2 - m) : 0.f);
#pragma unroll
    for (int o = 16; o; o >>= 1) s += __shfl_xor_sync(0xffffffffu, s, o);
    float lse = m + logf(s);
    out[(long long)n * 40 + lane] = v1 - lse;
    if (lane < 8) out[(long long)n * 40 + 32 + lane] = v2 - lse;
}

// ---------------- launch ----------------
extern "C" void kernel_launch(void* const* d_in, const int* in_sizes, int n_in,
                              void* d_out, int out_size)
{
    const float* x      = (const float*)d_in[0];
    const int*   eidx   = (const int*)  d_in[1];
    const float* eattr  = (const float*)d_in[2];
    const float* W1     = (const float*)d_in[3];
    const float* asrc1  = (const float*)d_in[4];
    const float* adst1  = (const float*)d_in[5];
    const float* aedge1 = (const float*)d_in[6];
    const float* W2     = (const float*)d_in[7];
    const float* asrc2  = (const float*)d_in[8];
    const float* adst2  = (const float*)d_in[9];
    const float* aedge2 = (const float*)d_in[10];
    float* out = (float*)d_out;

    const int* src = eidx;
    const int* dst = eidx + N_EDGES;

    clear_kernel<<<8192, 256>>>();
    gemm1_kernel<<<(N_NODES + 127) / 128, 128>>>(x, W1, asrc1, adst1);
    edge1_kernel<<<8192, 256>>>(src, dst, eattr, aedge1);
    gemm2_kernel<<<(N_NODES + 63) / 64, 256>>>(W2, asrc2, adst2);
    edge2_kernel<<<8192, 256>>>(src, dst, eattr, aedge2);
    finalize_kernel<<<(N_NODES * 32 + 255) / 256, 256>>>(out);
}

// round 2
// speedup vs baseline: 1.2910x; 1.2910x over previous
#include <cuda_runtime.h>
#include <math.h>

#define N_NODES 100000
#define N_EDGES 1600000
#define NB_SCAN ((N_NODES + 255) / 256)   // 391

// ---- scratch (device globals: allocation-free per harness rules) ----
__device__ float g_h1[N_NODES * 64];     // layer1 projected features
__device__ float g_ssrc1[N_NODES * 8];   // per-node src attention score (layer1)
__device__ float g_sdst1[N_NODES * 8];
__device__ float g_z1[N_NODES * 64];     // layer1 output: normalized + ELU
__device__ float g_h2[N_NODES * 40];     // layer2 projected features
__device__ float g_ssrc2[N_NODES];
__device__ float g_sdst2[N_NODES];

// ---- CSR scratch ----
__device__ int  g_deg[N_NODES];
__device__ int  g_off[N_NODES + 1];
__device__ int  g_cur[N_NODES];
__device__ int  g_bsum[NB_SCAN];
__device__ int  g_bexcl[NB_SCAN];
__device__ int2 g_cpack[N_EDGES];        // (src, edge_attr bits) sorted by dst

// ================= CSR build =================
__global__ void clear_deg_kernel() {
    int i = blockIdx.x * blockDim.x + threadIdx.x;
    if (i < N_NODES) g_deg[i] = 0;
}

__global__ void hist_kernel(const int* __restrict__ dst) {
    int i = blockIdx.x * blockDim.x + threadIdx.x;
    int stride = gridDim.x * blockDim.x;
    for (int e = i; e < N_EDGES; e += stride)
        atomicAdd(&g_deg[__ldg(&dst[e])], 1);
}

__global__ void scan1_kernel() {
    __shared__ int sh[256];
    int tid = threadIdx.x;
    int i = blockIdx.x * 256 + tid;
    sh[tid] = (i < N_NODES) ? g_deg[i] : 0;
    __syncthreads();
#pragma unroll
    for (int o = 128; o; o >>= 1) {
        if (tid < o) sh[tid] += sh[tid + o];
        __syncthreads();
    }
    if (tid == 0) g_bsum[blockIdx.x] = sh[0];
}

__global__ void scan2_kernel() {
    __shared__ int sh[512];
    int t = threadIdx.x;
    int v = (t < NB_SCAN) ? g_bsum[t] : 0;
    sh[t] = v;
    __syncthreads();
    for (int o = 1; o < 512; o <<= 1) {
        int x = 0;
        if (t >= o) x = sh[t - o];
        __syncthreads();
        sh[t] += x;
        __syncthreads();
    }
    if (t < NB_SCAN) g_bexcl[t] = sh[t] - v;
    if (t == 0) g_off[N_NODES] = N_EDGES;
}

__global__ void scan3_kernel() {
    int tid = threadIdx.x;
    int lane = tid & 31, wid = tid >> 5;
    int i = blockIdx.x * 256 + tid;
    int v = (i < N_NODES) ? g_deg[i] : 0;
    int incl = v;
#pragma unroll
    for (int o = 1; o < 32; o <<= 1) {
        int t = __shfl_up_sync(0xffffffffu, incl, o);
        if (lane >= o) incl += t;
    }
    __shared__ int wsum[8];
    if (lane == 31) wsum[wid] = incl;
    __syncthreads();
    if (tid < 8) {
        int x = wsum[tid];
#pragma unroll
        for (int o = 1; o < 8; o <<= 1) {
            int t = __shfl_up_sync(0xffu, x, o);
            if (tid >= o) x += t;
        }
        wsum[tid] = x;
    }
    __syncthreads();
    int base = g_bexcl[blockIdx.x] + (wid ? wsum[wid - 1] : 0);
    int excl = base + incl - v;
    if (i < N_NODES) { g_off[i] = excl; g_cur[i] = excl; }
}

__global__ void scatter_kernel(const int* __restrict__ src,
                               const int* __restrict__ dst,
                               const float* __restrict__ ea) {
    int i = blockIdx.x * blockDim.x + threadIdx.x;
    int stride = gridDim.x * blockDim.x;
    for (int e = i; e < N_EDGES; e += stride) {
        int d = __ldg(&dst[e]);
        int slot = atomicAdd(&g_cur[d], 1);
        g_cpack[slot] = make_int2(__ldg(&src[e]), __float_as_int(__ldg(&ea[e])));
    }
}

// ================= GEMM1: h1 = x @ W1, + s_src1/s_dst1 epilogue =================
__global__ void __launch_bounds__(128) gemm1_kernel(
    const float* __restrict__ x, const float* __restrict__ W1,
    const float* __restrict__ asrc, const float* __restrict__ adst)
{
    __shared__ float sx[128 * 33];
    __shared__ float sW[32 * 64];
    int tid = threadIdx.x;
    int ty = tid >> 3, tx = tid & 7;
    int base = blockIdx.x * 128;

    float acc[8][8];
#pragma unroll
    for (int i = 0; i < 8; i++)
#pragma unroll
        for (int j = 0; j < 8; j++) acc[i][j] = 0.f;

    for (int k0 = 0; k0 < 128; k0 += 32) {
#pragma unroll
        for (int t = tid; t < 1024; t += 128) {
            int row = t >> 3, q = t & 7;
            int node = base + row;
            float4 v = make_float4(0.f, 0.f, 0.f, 0.f);
            if (node < N_NODES)
                v = *(const float4*)&x[(long long)node * 128 + k0 + q * 4];
            float* sp = &sx[row * 33 + q * 4];
            sp[0] = v.x; sp[1] = v.y; sp[2] = v.z; sp[3] = v.w;
        }
#pragma unroll
        for (int t = tid; t < 512; t += 128) {
            int r = t >> 4, c4 = t & 15;
            *(float4*)&sW[r * 64 + c4 * 4] = *(const float4*)&W1[(k0 + r) * 64 + c4 * 4];
        }
        __syncthreads();
#pragma unroll 8
        for (int kk = 0; kk < 32; kk++) {
            float xa[8];
#pragma unroll
            for (int i = 0; i < 8; i++) xa[i] = sx[(ty * 8 + i) * 33 + kk];
            float4 w0 = *(float4*)&sW[kk * 64 + tx * 8];
            float4 w1 = *(float4*)&sW[kk * 64 + tx * 8 + 4];
            float wb[8] = {w0.x, w0.y, w0.z, w0.w, w1.x, w1.y, w1.z, w1.w};
#pragma unroll
            for (int i = 0; i < 8; i++)
#pragma unroll
                for (int j = 0; j < 8; j++) acc[i][j] += xa[i] * wb[j];
        }
        __syncthreads();
    }

    float as[8], ad[8];
#pragma unroll
    for (int j = 0; j < 8; j++) { as[j] = __ldg(&asrc[tx * 8 + j]); ad[j] = __ldg(&adst[tx * 8 + j]); }

#pragma unroll
    for (int i = 0; i < 8; i++) {
        int node = base + ty * 8 + i;
        if (node < N_NODES) {
            *(float4*)&g_h1[(long long)node * 64 + tx * 8] =
                make_float4(acc[i][0], acc[i][1], acc[i][2], acc[i][3]);
            *(float4*)&g_h1[(long long)node * 64 + tx * 8 + 4] =
                make_float4(acc[i][4], acc[i][5], acc[i][6], acc[i][7]);
            float ss = 0.f, sd = 0.f;
#pragma unroll
            for (int j = 0; j < 8; j++) { ss += acc[i][j] * as[j]; sd += acc[i][j] * ad[j]; }
            g_ssrc1[node * 8 + tx] = ss;
            g_sdst1[node * 8 + tx] = sd;
        }
    }
}

// ================= edge pass 1 (gather): warp per dst node =================
// lane i owns output dims {2i, 2i+1}, head h = i>>2. Fuses normalize + ELU.
__global__ void __launch_bounds__(256) edge1g_kernel(const float* __restrict__ aedge)
{
    int warp = threadIdx.x >> 5, lane = threadIdx.x & 31;
    int n = blockIdx.x * 8 + warp;
    if (n >= N_NODES) return;
    int h = lane >> 2;
    float ae = __ldg(&aedge[h]);
    float sd = g_sdst1[n * 8 + h];
    int beg = g_off[n], end = g_off[n + 1];

    float accx = 0.f, accy = 0.f, den = 0.f;
    int e = beg;
    for (; e + 1 < end; e += 2) {
        int2 p0 = g_cpack[e];
        int2 p1 = g_cpack[e + 1];
        int s0 = p0.x, s1 = p1.x;
        float ls0 = g_ssrc1[s0 * 8 + h];
        float ls1 = g_ssrc1[s1 * 8 + h];
        float2 hv0 = *(const float2*)&g_h1[(long long)s0 * 64 + lane * 2];
        float2 hv1 = *(const float2*)&g_h1[(long long)s1 * 64 + lane * 2];
        float lg0 = ls0 + sd + __int_as_float(p0.y) * ae;
        float lg1 = ls1 + sd + __int_as_float(p1.y) * ae;
        lg0 = lg0 > 0.f ? lg0 : 0.2f * lg0;
        lg1 = lg1 > 0.f ? lg1 : 0.2f * lg1;
        float w0 = __expf(lg0), w1 = __expf(lg1);
        accx = fmaf(w0, hv0.x, fmaf(w1, hv1.x, accx));
        accy = fmaf(w0, hv0.y, fmaf(w1, hv1.y, accy));
        den += w0 + w1;
    }
    if (e < end) {
        int2 p0 = g_cpack[e];
        int s0 = p0.x;
        float ls0 = g_ssrc1[s0 * 8 + h];
        float2 hv0 = *(const float2*)&g_h1[(long long)s0 * 64 + lane * 2];
        float lg0 = ls0 + sd + __int_as_float(p0.y) * ae;
        lg0 = lg0 > 0.f ? lg0 : 0.2f * lg0;
        float w0 = __expf(lg0);
        accx = fmaf(w0, hv0.x, accx);
        accy = fmaf(w0, hv0.y, accy);
        den += w0;
    }
    float inv = 1.0f / (den + 1e-16f);
    float vx = accx * inv, vy = accy * inv;
    vx = vx > 0.f ? vx : expm1f(vx);   // ELU
    vy = vy > 0.f ? vy : expm1f(vy);
    *(float2*)&g_z1[(long long)n * 64 + lane * 2] = make_float2(vx, vy);
}

// ================= GEMM2: h2 = z1 @ W2, + s_src2/s_dst2 =================
// 128 threads / 128 nodes per block; thread owns a node, 40 cols in registers.
__global__ void __launch_bounds__(128) gemm2_kernel(
    const float* __restrict__ W2, const float* __restrict__ asrc,
    const float* __restrict__ adst)
{
    __shared__ float sx[128 * 65];
    __shared__ float sW[64 * 40];
    __shared__ float sA[40], sD[40];
    int tid = threadIdx.x;
    int base = blockIdx.x * 128;

    for (int t = tid; t < 2560; t += 128) sW[t] = W2[t];
    if (tid < 40) { sA[tid] = asrc[tid]; sD[tid] = adst[tid]; }

#pragma unroll
    for (int t = tid; t < 2048; t += 128) {
        int row = t >> 4, q = t & 15;
        int node = base + row;
        float4 v = make_float4(0.f, 0.f, 0.f, 0.f);
        if (node < N_NODES)
            v = *(const float4*)&g_z1[(long long)node * 64 + q * 4];
        float* sp = &sx[row * 65 + q * 4];
        sp[0] = v.x; sp[1] = v.y; sp[2] = v.z; sp[3] = v.w;
    }
    __syncthreads();

    float4 a[10];
#pragma unroll
    for (int j = 0; j < 10; j++) a[j] = make_float4(0.f, 0.f, 0.f, 0.f);

#pragma unroll 4
    for (int k = 0; k < 64; k++) {
        float xv = sx[tid * 65 + k];
#pragma unroll
        for (int j = 0; j < 10; j++) {
            float4 w = *(const float4*)&sW[k * 40 + j * 4];
            a[j].x = fmaf(xv, w.x, a[j].x);
            a[j].y = fmaf(xv, w.y, a[j].y);
            a[j].z = fmaf(xv, w.z, a[j].z);
            a[j].w = fmaf(xv, w.w, a[j].w);
        }
    }

    int node = base + tid;
    if (node < N_NODES) {
        float ss = 0.f, sd = 0.f;
#pragma unroll
        for (int j = 0; j < 10; j++) {
            ss += a[j].x * sA[j * 4] + a[j].y * sA[j * 4 + 1] + a[j].z * sA[j * 4 + 2] + a[j].w * sA[j * 4 + 3];
            sd += a[j].x * sD[j * 4] + a[j].y * sD[j * 4 + 1] + a[j].z * sD[j * 4 + 2] + a[j].w * sD[j * 4 + 3];
            *(float4*)&g_h2[(long long)node * 40 + j * 4] = a[j];
        }
        g_ssrc2[node] = ss;
        g_sdst2[node] = sd;
    }
}

// ================= edge pass 2 (gather) + fused log_softmax =================
// warp per dst node; lanes 0..19 own dims {2i,2i+1} of 40.
__global__ void __launch_bounds__(256) edge2g_kernel(
    const float* __restrict__ aedge2, float* __restrict__ out)
{
    int warp = threadIdx.x >> 5, lane = threadIdx.x & 31;
    int n = blockIdx.x * 8 + warp;
    if (n >= N_NODES) return;
    float ae = __ldg(&aedge2[0]);
    float sd = g_sdst2[n];
    int beg = g_off[n], end = g_off[n + 1];
    bool act = lane < 20;

    float accx = 0.f, accy = 0.f, den = 0.f;
    int e = beg;
    for (; e + 1 < end; e += 2) {
        int2 p0 = g_cpack[e];
        int2 p1 = g_cpack[e + 1];
        int s0 = p0.x, s1 = p1.x;
        float ls0 = g_ssrc2[s0];
        float ls1 = g_ssrc2[s1];
        float2 hv0 = make_float2(0.f, 0.f), hv1 = make_float2(0.f, 0.f);
        if (act) {
            hv0 = *(const float2*)&g_h2[(long long)s0 * 40 + lane * 2];
            hv1 = *(const float2*)&g_h2[(long long)s1 * 40 + lane * 2];
        }
        float lg0 = ls0 + sd + __int_as_float(p0.y) * ae;
        float lg1 = ls1 + sd + __int_as_float(p1.y) * ae;
        lg0 = lg0 > 0.f ? lg0 : 0.2f * lg0;
        lg1 = lg1 > 0.f ? lg1 : 0.2f * lg1;
        float w0 = __expf(lg0), w1 = __expf(lg1);
        accx = fmaf(w0, hv0.x, fmaf(w1, hv1.x, accx));
        accy = fmaf(w0, hv0.y, fmaf(w1, hv1.y, accy));
        den += w0 + w1;
    }
    if (e < end) {
        int2 p0 = g_cpack[e];
        int s0 = p0.x;
        float ls0 = g_ssrc2[s0];
        float2 hv0 = make_float2(0.f, 0.f);
        if (act) hv0 = *(const float2*)&g_h2[(long long)s0 * 40 + lane * 2];
        float lg0 = ls0 + sd + __int_as_float(p0.y) * ae;
        lg0 = lg0 > 0.f ? lg0 : 0.2f * lg0;
        float w0 = __expf(lg0);
        accx = fmaf(w0, hv0.x, accx);
        accy = fmaf(w0, hv0.y, accy);
        den += w0;
    }
    float inv = 1.0f / (den + 1e-16f);
    float vx = accx * inv, vy = accy * inv;

    // log_softmax over the 40 values spread across lanes 0..19
    float m = act ? fmaxf(vx, vy) : -INFINITY;
#pragma unroll
    for (int o = 16; o; o >>= 1) m = fmaxf(m, __shfl_xor_sync(0xffffffffu, m, o));
    float s = act ? (__expf(vx - m) + __expf(vy - m)) : 0.f;
#pragma unroll
    for (int o = 16; o; o >>= 1) s += __shfl_xor_sync(0xffffffffu, s, o);
    float lse = m + logf(s);
    if (act)
        *(float2*)&out[(long long)n * 40 + lane * 2] = make_float2(vx - lse, vy - lse);
}

// ================= launch =================
extern "C" void kernel_launch(void* const* d_in, const int* in_sizes, int n_in,
                              void* d_out, int out_size)
{
    const float* x      = (const float*)d_in[0];
    const int*   eidx   = (const int*)  d_in[1];
    const float* eattr  = (const float*)d_in[2];
    const float* W1     = (const float*)d_in[3];
    const float* asrc1  = (const float*)d_in[4];
    const float* adst1  = (const float*)d_in[5];
    const float* aedge1 = (const float*)d_in[6];
    const float* W2     = (const float*)d_in[7];
    const float* asrc2  = (const float*)d_in[8];
    const float* adst2  = (const float*)d_in[9];
    const float* aedge2 = (const float*)d_in[10];
    float* out = (float*)d_out;

    const int* src = eidx;
    const int* dst = eidx + N_EDGES;

    clear_deg_kernel<<<(N_NODES + 255) / 256, 256>>>();
    gemm1_kernel<<<(N_NODES + 127) / 128, 128>>>(x, W1, asrc1, adst1);   // overlaps nothing but independent of CSR
    hist_kernel<<<4096, 256>>>(dst);
    scan1_kernel<<<NB_SCAN, 256>>>();
    scan2_kernel<<<1, 512>>>();
    scan3_kernel<<<NB_SCAN, 256>>>();
    scatter_kernel<<<4096, 256>>>(src, dst, eattr);
    edge1g_kernel<<<(N_NODES + 7) / 8, 256>>>(aedge1);
    gemm2_kernel<<<(N_NODES + 127) / 128, 128>>>(W2, asrc2, adst2);
    edge2g_kernel<<<(N_NODES + 7) / 8, 256>>>(aedge2, out);
}